// round 2
// baseline (speedup 1.0000x reference)
#include <cuda_runtime.h>
#include <math.h>

#define NN 50000
#define EE 800000
#define HH 128
#define CC 10
#define GG 128
#define NBLK 196   // ceil(NN/256)

// ---------------- device scratch (static, no allocation) ----------------
__device__ int   g_outdeg[NN];
__device__ int   g_indeg[NN];
__device__ float g_csrc[NN];
__device__ float g_cdst[NN];
__device__ int   g_rowptr[NN + 1];
__device__ int   g_fill[NN];
__device__ int   g_col[EE];
__device__ float g_m[NN * HH];
__device__ float g_h1[NN * HH];
__device__ float g_h2[NN * HH];
__device__ float g_hg[GG * HH];
__device__ int   g_part[NBLK + 64];
__device__ int   g_partex[NBLK + 64];

// ---------------- f32x2 helpers ----------------
__device__ __forceinline__ unsigned long long dup2(float a) {
    unsigned long long r;
    asm("mov.b64 %0, {%1, %1};" : "=l"(r) : "f"(a));
    return r;
}
__device__ __forceinline__ void fma2(unsigned long long& acc,
                                     unsigned long long a,
                                     unsigned long long b) {
    asm("fma.rn.f32x2 %0, %1, %2, %0;" : "+l"(acc) : "l"(a), "l"(b));
}
union U2 { unsigned long long u; float2 f; };

// ---------------- preprocessing kernels ----------------

__global__ void zero_kernel() {
    int i = blockIdx.x * blockDim.x + threadIdx.x;
    if (i < NN) { g_outdeg[i] = 0; g_indeg[i] = 0; }
}

__global__ void degree_kernel(const int* __restrict__ ei) {
    int e = blockIdx.x * blockDim.x + threadIdx.x;
    if (e >= EE) return;
    atomicAdd(&g_outdeg[ei[e]], 1);
    atomicAdd(&g_indeg[ei[EE + e]], 1);
}

// pass 1: per-block sums of indeg + norm coefficients
__global__ void scan_p1() {
    int t = threadIdx.x;
    int i = blockIdx.x * 256 + t;
    int v = 0;
    if (i < NN) {
        v = g_indeg[i];
        g_csrc[i] = rsqrtf(fmaxf((float)g_outdeg[i], 1.0f));
        g_cdst[i] = rsqrtf(fmaxf((float)v, 1.0f));
    }
    // block reduce
    int lane = t & 31, w = t >> 5;
    int x = v;
    #pragma unroll
    for (int o = 16; o > 0; o >>= 1) x += __shfl_down_sync(~0u, x, o);
    __shared__ int ws[8];
    if (lane == 0) ws[w] = x;
    __syncthreads();
    if (t == 0) {
        int s = 0;
        #pragma unroll
        for (int j = 0; j < 8; j++) s += ws[j];
        g_part[blockIdx.x] = s;
    }
}

// pass 2: scan the 196 block sums (1 block, 256 threads)
__global__ void scan_p2() {
    int t = threadIdx.x;
    int v = (t < NBLK) ? g_part[t] : 0;
    int lane = t & 31, w = t >> 5;
    int x = v;
    #pragma unroll
    for (int o = 1; o < 32; o <<= 1) {
        int y = __shfl_up_sync(~0u, x, o);
        if (lane >= o) x += y;
    }
    __shared__ int ws[8];
    if (lane == 31) ws[w] = x;
    __syncthreads();
    if (t < 8) {
        int s = ws[t];
        #pragma unroll
        for (int o = 1; o < 8; o <<= 1) {
            int y = __shfl_up_sync(0xff, s, o);
            if (t >= o) s += y;
        }
        ws[t] = s;
    }
    __syncthreads();
    int incl = x + (w > 0 ? ws[w - 1] : 0);
    if (t < NBLK) g_partex[t] = incl - v;
    if (t == NBLK - 1) g_rowptr[NN] = incl;
}

// pass 3: per-block rescan + add block offset -> rowptr / fill
__global__ void scan_p3() {
    int t = threadIdx.x;
    int i = blockIdx.x * 256 + t;
    int v = (i < NN) ? g_indeg[i] : 0;
    int lane = t & 31, w = t >> 5;
    int x = v;
    #pragma unroll
    for (int o = 1; o < 32; o <<= 1) {
        int y = __shfl_up_sync(~0u, x, o);
        if (lane >= o) x += y;
    }
    __shared__ int ws[8];
    if (lane == 31) ws[w] = x;
    __syncthreads();
    if (t < 8) {
        int s = ws[t];
        #pragma unroll
        for (int o = 1; o < 8; o <<= 1) {
            int y = __shfl_up_sync(0xff, s, o);
            if (t >= o) s += y;
        }
        ws[t] = s;
    }
    __syncthreads();
    int excl = x - v + (w > 0 ? ws[w - 1] : 0) + g_partex[blockIdx.x];
    if (i < NN) { g_rowptr[i] = excl; g_fill[i] = excl; }
}

__global__ void csr_fill_kernel(const int* __restrict__ ei) {
    int e = blockIdx.x * blockDim.x + threadIdx.x;
    if (e >= EE) return;
    int d = ei[EE + e];
    int pos = atomicAdd(&g_fill[d], 1);
    g_col[pos] = ei[e];
}

// ---------------- SpMM: one warp per destination row ----------------
__global__ void spmm_kernel(const float* __restrict__ hin, float* __restrict__ mout) {
    int gw = (blockIdx.x * blockDim.x + threadIdx.x) >> 5;
    int lane = threadIdx.x & 31;
    if (gw >= NN) return;
    int e0 = g_rowptr[gw];
    int e1 = g_rowptr[gw + 1];
    const float4* h4 = (const float4*)hin;
    float4 acc = make_float4(0.f, 0.f, 0.f, 0.f);
    for (int e = e0; e < e1; e++) {
        int s = g_col[e];
        float cs = g_csrc[s];
        float4 v = h4[s * 32 + lane];
        acc.x = fmaf(cs, v.x, acc.x);
        acc.y = fmaf(cs, v.y, acc.y);
        acc.z = fmaf(cs, v.z, acc.z);
        acc.w = fmaf(cs, v.w, acc.w);
    }
    float cd = g_cdst[gw];
    ((float4*)mout)[gw * 32 + lane] =
        make_float4(acc.x * cd, acc.y * cd, acc.z * cd, acc.w * cd);
}

// ---------------- GEMM+ReLU with packed f32x2 FMA ----------------
// 64 rows x 128 cols per block, 256 threads.
// thread: 2 rows (ty*2, ty*2+1) x 16 cols (tx*16..+15) -> 16 f32x2 accumulators
#define APITCH 129
__global__ __launch_bounds__(256) void gemm_relu_kernel(
    const float* __restrict__ A, const float* __restrict__ W,
    const float* __restrict__ bias, float* __restrict__ out) {
    extern __shared__ float sm[];
    float* sW = sm;                 // [128][128]
    float* sA = sm + 128 * 128;     // [64][129] padded
    const int t = threadIdx.x;
    const int row0 = blockIdx.x * 64;

    // load W (coalesced float4)
    const float4* W4 = (const float4*)W;
    #pragma unroll
    for (int i = t; i < 128 * 32; i += 256) ((float4*)sW)[i] = W4[i];

    // load A tile into padded smem
    const float4* A4 = (const float4*)A;
    #pragma unroll
    for (int i = t; i < 64 * 32; i += 256) {
        int r = i >> 5, kq = i & 31;
        float4 v = make_float4(0.f, 0.f, 0.f, 0.f);
        if (row0 + r < NN) v = A4[(row0 + r) * 32 + kq];
        float* dst = sA + r * APITCH + kq * 4;
        dst[0] = v.x; dst[1] = v.y; dst[2] = v.z; dst[3] = v.w;
    }
    __syncthreads();

    const int tx = t & 7;    // col group: 16 cols
    const int ty = t >> 3;   // row pair
    const int r0 = ty * 2;

    unsigned long long acc0[8], acc1[8];
    #pragma unroll
    for (int p = 0; p < 8; p++) { acc0[p] = 0ull; acc1[p] = 0ull; }

    const ulonglong2* sWu = (const ulonglong2*)sW;  // 32 x ulonglong2 per k-row
    const float* a0p = sA + r0 * APITCH;
    const float* a1p = sA + (r0 + 1) * APITCH;

    #pragma unroll 4
    for (int k = 0; k < 128; k++) {
        unsigned long long a0 = dup2(a0p[k]);
        unsigned long long a1 = dup2(a1p[k]);
        #pragma unroll
        for (int q = 0; q < 4; q++) {
            ulonglong2 w = sWu[k * 32 + tx * 4 + q];
            fma2(acc0[q * 2 + 0], a0, w.x);
            fma2(acc0[q * 2 + 1], a0, w.y);
            fma2(acc1[q * 2 + 0], a1, w.x);
            fma2(acc1[q * 2 + 1], a1, w.y);
        }
    }

    // epilogue: bias + relu + store
    const float4* b4 = (const float4*)bias;
    float4* out4 = (float4*)out;
    #pragma unroll
    for (int q = 0; q < 4; q++) {
        float4 bv = b4[tx * 4 + q];
        U2 u0a, u0b, u1a, u1b;
        u0a.u = acc0[q * 2 + 0]; u0b.u = acc0[q * 2 + 1];
        u1a.u = acc1[q * 2 + 0]; u1b.u = acc1[q * 2 + 1];
        int ra = row0 + r0;
        if (ra < NN) {
            float4 o;
            o.x = fmaxf(u0a.f.x + bv.x, 0.f);
            o.y = fmaxf(u0a.f.y + bv.y, 0.f);
            o.z = fmaxf(u0b.f.x + bv.z, 0.f);
            o.w = fmaxf(u0b.f.y + bv.w, 0.f);
            out4[ra * 32 + tx * 4 + q] = o;
        }
        int rb = row0 + r0 + 1;
        if (rb < NN) {
            float4 o;
            o.x = fmaxf(u1a.f.x + bv.x, 0.f);
            o.y = fmaxf(u1a.f.y + bv.y, 0.f);
            o.z = fmaxf(u1b.f.x + bv.z, 0.f);
            o.w = fmaxf(u1b.f.y + bv.w, 0.f);
            out4[rb * 32 + tx * 4 + q] = o;
        }
    }
}

// ---------------- readout: one block per graph, binary search, no atomics ----
__global__ void readout_kernel(const float* __restrict__ h, const int* __restrict__ gid) {
    int g = blockIdx.x;        // 0..127
    int f = threadIdx.x;       // 0..127 feature
    // lower_bound(gid, g) and lower_bound(gid, g+1) over sorted gid[0..NN)
    int lo = 0, hi = NN;
    while (lo < hi) { int mid = (lo + hi) >> 1; if (gid[mid] < g) lo = mid + 1; else hi = mid; }
    int start = lo;
    lo = start; hi = NN;
    while (lo < hi) { int mid = (lo + hi) >> 1; if (gid[mid] < g + 1) lo = mid + 1; else hi = mid; }
    int end = lo;

    float s = 0.f;
    for (int n = start; n < end; n++) s += h[n * HH + f];
    float cnt = (float)(end - start);
    g_hg[g * HH + f] = s / fmaxf(cnt, 1.0f);
}

__global__ void final_kernel(const float* __restrict__ Wc, const float* __restrict__ bc,
                             float* __restrict__ out) {
    int idx = blockIdx.x * blockDim.x + threadIdx.x;
    if (idx >= GG * CC) return;
    int g = idx / CC, c = idx % CC;
    float sum = 0.f;
    #pragma unroll 8
    for (int k = 0; k < HH; k++) sum = fmaf(g_hg[g * HH + k], Wc[k * CC + c], sum);
    out[idx] = sum + bc[c];
}

// ---------------- host launcher ----------------
extern "C" void kernel_launch(void* const* d_in, const int* in_sizes, int n_in,
                              void* d_out, int out_size) {
    const float* x   = (const float*)d_in[0];
    const float* W0  = (const float*)d_in[1];
    const float* b0  = (const float*)d_in[2];
    const float* Ws  = (const float*)d_in[3];
    const float* bs  = (const float*)d_in[4];
    const float* Wc  = (const float*)d_in[5];
    const float* bc  = (const float*)d_in[6];
    const int*   ei  = (const int*)d_in[7];
    const int*   gid = (const int*)d_in[8];
    float* out = (float*)d_out;

    float *h1, *h2, *m;
    cudaGetSymbolAddress((void**)&h1, g_h1);
    cudaGetSymbolAddress((void**)&h2, g_h2);
    cudaGetSymbolAddress((void**)&m,  g_m);

    const int GEMM_SMEM = (128 * 128 + 64 * APITCH) * (int)sizeof(float);
    cudaFuncSetAttribute(gemm_relu_kernel,
                         cudaFuncAttributeMaxDynamicSharedMemorySize, GEMM_SMEM);

    // graph preprocessing
    zero_kernel<<<(NN + 255) / 256, 256>>>();
    degree_kernel<<<(EE + 255) / 256, 256>>>(ei);
    scan_p1<<<NBLK, 256>>>();
    scan_p2<<<1, 256>>>();
    scan_p3<<<NBLK, 256>>>();
    csr_fill_kernel<<<(EE + 255) / 256, 256>>>(ei);

    const int SPMM_BLOCKS = (NN + 7) / 8;
    const int GEMM_BLOCKS = (NN + 63) / 64;

    spmm_kernel<<<SPMM_BLOCKS, 256>>>(x, m);
    gemm_relu_kernel<<<GEMM_BLOCKS, 256, GEMM_SMEM>>>(m, W0, b0, h1);
    spmm_kernel<<<SPMM_BLOCKS, 256>>>(h1, m);
    gemm_relu_kernel<<<GEMM_BLOCKS, 256, GEMM_SMEM>>>(m, Ws + 0 * 128 * 128, bs + 0 * 128, h2);
    spmm_kernel<<<SPMM_BLOCKS, 256>>>(h2, m);
    gemm_relu_kernel<<<GEMM_BLOCKS, 256, GEMM_SMEM>>>(m, Ws + 1 * 128 * 128, bs + 1 * 128, h1);
    spmm_kernel<<<SPMM_BLOCKS, 256>>>(h1, m);
    gemm_relu_kernel<<<GEMM_BLOCKS, 256, GEMM_SMEM>>>(m, Ws + 2 * 128 * 128, bs + 2 * 128, h2);

    readout_kernel<<<GG, HH>>>(h2, gid);
    final_kernel<<<(GG * CC + 127) / 128, 128>>>(Wc, bc, out);
}

// round 3
// speedup vs baseline: 2.7656x; 2.7656x over previous
#include <cuda_runtime.h>
#include <math.h>

#define NN 50000
#define EE 800000
#define HH 128
#define CC 10
#define GG 128
#define NBLK 196   // ceil(NN/256)

// ---------------- device scratch (static, no allocation) ----------------
__device__ int   g_outdeg[NN];
__device__ int   g_indeg[NN];
__device__ float g_csrc[NN];
__device__ float g_cdst[NN];
__device__ int   g_rowptr[NN + 1];
__device__ int   g_fill[NN];
__device__ int   g_col[EE];
__device__ float g_m[NN * HH];
__device__ float g_h1[NN * HH];
__device__ float g_h2[NN * HH];
__device__ float g_hg[GG * HH];
__device__ int   g_part[NBLK];

// ---------------- f32x2 helpers ----------------
__device__ __forceinline__ unsigned long long dup2(float a) {
    unsigned long long r;
    asm("mov.b64 %0, {%1, %1};" : "=l"(r) : "f"(a));
    return r;
}
__device__ __forceinline__ void fma2(unsigned long long& acc,
                                     unsigned long long a,
                                     unsigned long long b) {
    asm("fma.rn.f32x2 %0, %1, %2, %0;" : "+l"(acc) : "l"(a), "l"(b));
}
union U2 { unsigned long long u; float2 f; };

// ---------------- preprocessing ----------------

__global__ void zero_kernel() {
    int i = blockIdx.x * blockDim.x + threadIdx.x;
    if (i < NN) { g_outdeg[i] = 0; g_indeg[i] = 0; }
    if (i == 0) g_rowptr[NN] = EE;
}

__global__ void degree_kernel(const int* __restrict__ ei) {
    int e = blockIdx.x * blockDim.x + threadIdx.x;
    if (e >= EE) return;
    atomicAdd(&g_outdeg[ei[e]], 1);
    atomicAdd(&g_indeg[ei[EE + e]], 1);
}

// pass 1: per-block sums of indeg + norm coefficients
__global__ void scan_p1() {
    int t = threadIdx.x;
    int i = blockIdx.x * 256 + t;
    int v = 0;
    if (i < NN) {
        v = g_indeg[i];
        g_csrc[i] = rsqrtf(fmaxf((float)g_outdeg[i], 1.0f));
        g_cdst[i] = rsqrtf(fmaxf((float)v, 1.0f));
    }
    int lane = t & 31, w = t >> 5;
    int x = v;
    #pragma unroll
    for (int o = 16; o > 0; o >>= 1) x += __shfl_down_sync(~0u, x, o);
    __shared__ int ws[8];
    if (lane == 0) ws[w] = x;
    __syncthreads();
    if (t == 0) {
        int s = 0;
        #pragma unroll
        for (int j = 0; j < 8; j++) s += ws[j];
        g_part[blockIdx.x] = s;
    }
}

// pass 2 (merged): each block computes its own offset from g_part, then rescans
__global__ void scan_p3() {
    __shared__ int rs[8];
    __shared__ int ss[8];
    __shared__ int s_off;
    const int t = threadIdx.x, bid = blockIdx.x;
    const int lane = t & 31, w = t >> 5;

    // exclusive prefix of block sums: sum g_part[0..bid)
    int p = 0;
    for (int j = t; j < bid; j += 256) p += g_part[j];
    int pr = p;
    #pragma unroll
    for (int o = 16; o > 0; o >>= 1) pr += __shfl_down_sync(~0u, pr, o);
    if (lane == 0) rs[w] = pr;
    __syncthreads();
    if (t == 0) {
        int s = 0;
        #pragma unroll
        for (int j = 0; j < 8; j++) s += rs[j];
        s_off = s;
    }
    __syncthreads();
    const int off = s_off;

    // intra-block inclusive scan of indeg
    int i = bid * 256 + t;
    int v = (i < NN) ? g_indeg[i] : 0;
    int x = v;
    #pragma unroll
    for (int o = 1; o < 32; o <<= 1) {
        int y = __shfl_up_sync(~0u, x, o);
        if (lane >= o) x += y;
    }
    if (lane == 31) ss[w] = x;
    __syncthreads();
    if (t < 8) {
        int s = ss[t];
        #pragma unroll
        for (int o = 1; o < 8; o <<= 1) {
            int y = __shfl_up_sync(0xff, s, o);
            if (t >= o) s += y;
        }
        ss[t] = s;
    }
    __syncthreads();
    int excl = x - v + (w > 0 ? ss[w - 1] : 0) + off;
    if (i < NN) { g_rowptr[i] = excl; g_fill[i] = excl; }
}

__global__ void csr_fill_kernel(const int* __restrict__ ei) {
    int e = blockIdx.x * blockDim.x + threadIdx.x;
    if (e >= EE) return;
    int d = ei[EE + e];
    int pos = atomicAdd(&g_fill[d], 1);
    g_col[pos] = ei[e];
}

// ---------------- SpMM: one warp per destination row, 2-way edge unroll ------
__global__ void spmm_kernel(const float* __restrict__ hin, float* __restrict__ mout) {
    int gw = (blockIdx.x * blockDim.x + threadIdx.x) >> 5;
    int lane = threadIdx.x & 31;
    if (gw >= NN) return;
    int e0 = g_rowptr[gw];
    int e1 = g_rowptr[gw + 1];
    const float4* h4 = (const float4*)hin;
    float4 acc0 = make_float4(0.f, 0.f, 0.f, 0.f);
    float4 acc1 = make_float4(0.f, 0.f, 0.f, 0.f);
    int e = e0;
    for (; e + 2 <= e1; e += 2) {
        int s0 = g_col[e], s1 = g_col[e + 1];
        float c0 = g_csrc[s0], c1 = g_csrc[s1];
        float4 v0 = h4[s0 * 32 + lane];
        float4 v1 = h4[s1 * 32 + lane];
        acc0.x = fmaf(c0, v0.x, acc0.x);
        acc0.y = fmaf(c0, v0.y, acc0.y);
        acc0.z = fmaf(c0, v0.z, acc0.z);
        acc0.w = fmaf(c0, v0.w, acc0.w);
        acc1.x = fmaf(c1, v1.x, acc1.x);
        acc1.y = fmaf(c1, v1.y, acc1.y);
        acc1.z = fmaf(c1, v1.z, acc1.z);
        acc1.w = fmaf(c1, v1.w, acc1.w);
    }
    if (e < e1) {
        int s = g_col[e];
        float cs = g_csrc[s];
        float4 v = h4[s * 32 + lane];
        acc0.x = fmaf(cs, v.x, acc0.x);
        acc0.y = fmaf(cs, v.y, acc0.y);
        acc0.z = fmaf(cs, v.z, acc0.z);
        acc0.w = fmaf(cs, v.w, acc0.w);
    }
    float cd = g_cdst[gw];
    ((float4*)mout)[gw * 32 + lane] =
        make_float4((acc0.x + acc1.x) * cd, (acc0.y + acc1.y) * cd,
                    (acc0.z + acc1.z) * cd, (acc0.w + acc1.w) * cd);
}

// ---------------- GEMM+ReLU, packed f32x2, conflict-free smem ----------------
// 128 rows x 128 cols per block, 512 threads.
// Thread: 8 rows (ty*8..) x 4 cols (tx*4..) -> 16 u64 accumulators (32 regs).
// W in smem as-is (ulonglong2 per lane, R1's conflict-free LDS.128 pattern).
// A pre-duplicated in smem as {a,a} u64 -> hot loop uses LDS.64 broadcast.
#define GEMM_SMEM_BYTES (128 * 128 * 4 + 128 * 128 * 8)  // 192KB
__global__ __launch_bounds__(512) void gemm_relu_kernel(
    const float* __restrict__ A, const float* __restrict__ W,
    const float* __restrict__ bias, float* __restrict__ out) {
    extern __shared__ float sm[];
    float* sW = sm;                                                    // 64KB
    unsigned long long* sA2 = (unsigned long long*)(sm + 128 * 128);   // 128KB
    const int t = threadIdx.x;
    const int row0 = blockIdx.x * 128;

    // W: coalesced float4, conflict-free
    const float4* W4 = (const float4*)W;
    #pragma unroll
    for (int i = t; i < 128 * 32; i += 512) ((float4*)sW)[i] = W4[i];

    // A: scalar coalesced loads, consecutive-lane STS.64 (2-way max)
    #pragma unroll
    for (int i = t; i < 128 * 128; i += 512) {
        int r = i >> 7, k = i & 127;
        float a = 0.f;
        if (row0 + r < NN) a = A[(row0 + r) * 128 + k];
        sA2[r * 128 + k] = dup2(a);
    }
    __syncthreads();

    const int tx = t & 31;   // col group: 4 cols
    const int ty = t >> 5;   // row group: 8 rows
    const int r0 = ty * 8;

    unsigned long long acc[16];
    #pragma unroll
    for (int p = 0; p < 16; p++) acc[p] = 0ull;

    const ulonglong2* sWu = (const ulonglong2*)sW;

    #pragma unroll 2
    for (int k = 0; k < 128; k++) {
        ulonglong2 wv = sWu[k * 32 + tx];   // LDS.128, conflict-free
        #pragma unroll
        for (int j = 0; j < 8; j++) {
            unsigned long long a = sA2[(r0 + j) * 128 + k];  // broadcast
            fma2(acc[2 * j],     a, wv.x);
            fma2(acc[2 * j + 1], a, wv.y);
        }
    }

    float4 bv = ((const float4*)bias)[tx];
    float4* out4 = (float4*)out;
    #pragma unroll
    for (int j = 0; j < 8; j++) {
        int r = row0 + r0 + j;
        if (r < NN) {
            U2 ua, ub;
            ua.u = acc[2 * j]; ub.u = acc[2 * j + 1];
            float4 o;
            o.x = fmaxf(ua.f.x + bv.x, 0.f);
            o.y = fmaxf(ua.f.y + bv.y, 0.f);
            o.z = fmaxf(ub.f.x + bv.z, 0.f);
            o.w = fmaxf(ub.f.y + bv.w, 0.f);
            out4[r * 32 + tx] = o;
        }
    }
}

// ---------------- readout: one block per graph, binary search, no atomics ----
__global__ void readout_kernel(const float* __restrict__ h, const int* __restrict__ gid) {
    int g = blockIdx.x;
    int f = threadIdx.x;
    int lo = 0, hi = NN;
    while (lo < hi) { int mid = (lo + hi) >> 1; if (gid[mid] < g) lo = mid + 1; else hi = mid; }
    int start = lo;
    lo = start; hi = NN;
    while (lo < hi) { int mid = (lo + hi) >> 1; if (gid[mid] < g + 1) lo = mid + 1; else hi = mid; }
    int end = lo;

    float s = 0.f;
    for (int n = start; n < end; n++) s += h[n * HH + f];
    float cnt = (float)(end - start);
    g_hg[g * HH + f] = s / fmaxf(cnt, 1.0f);
}

__global__ void final_kernel(const float* __restrict__ Wc, const float* __restrict__ bc,
                             float* __restrict__ out) {
    int idx = blockIdx.x * blockDim.x + threadIdx.x;
    if (idx >= GG * CC) return;
    int g = idx / CC, c = idx % CC;
    float sum = 0.f;
    #pragma unroll 8
    for (int k = 0; k < HH; k++) sum = fmaf(g_hg[g * HH + k], Wc[k * CC + c], sum);
    out[idx] = sum + bc[c];
}

// ---------------- host launcher ----------------
extern "C" void kernel_launch(void* const* d_in, const int* in_sizes, int n_in,
                              void* d_out, int out_size) {
    const float* x   = (const float*)d_in[0];
    const float* W0  = (const float*)d_in[1];
    const float* b0  = (const float*)d_in[2];
    const float* Ws  = (const float*)d_in[3];
    const float* bs  = (const float*)d_in[4];
    const float* Wc  = (const float*)d_in[5];
    const float* bc  = (const float*)d_in[6];
    const int*   ei  = (const int*)d_in[7];
    const int*   gid = (const int*)d_in[8];
    float* out = (float*)d_out;

    float *h1, *h2, *m;
    cudaGetSymbolAddress((void**)&h1, g_h1);
    cudaGetSymbolAddress((void**)&h2, g_h2);
    cudaGetSymbolAddress((void**)&m,  g_m);

    cudaFuncSetAttribute(gemm_relu_kernel,
                         cudaFuncAttributeMaxDynamicSharedMemorySize, GEMM_SMEM_BYTES);

    // preprocessing (5 launches -> spmm is launch #6 for ncu -s 5 -c 1)
    zero_kernel<<<(NN + 255) / 256, 256>>>();
    degree_kernel<<<(EE + 255) / 256, 256>>>(ei);
    scan_p1<<<NBLK, 256>>>();
    scan_p3<<<NBLK, 256>>>();
    csr_fill_kernel<<<(EE + 255) / 256, 256>>>(ei);

    const int SPMM_BLOCKS = (NN + 7) / 8;
    const int GEMM_BLOCKS = (NN + 127) / 128;

    spmm_kernel<<<SPMM_BLOCKS, 256>>>(x, m);
    gemm_relu_kernel<<<GEMM_BLOCKS, 512, GEMM_SMEM_BYTES>>>(m, W0, b0, h1);
    spmm_kernel<<<SPMM_BLOCKS, 256>>>(h1, m);
    gemm_relu_kernel<<<GEMM_BLOCKS, 512, GEMM_SMEM_BYTES>>>(m, Ws + 0 * 128 * 128, bs + 0 * 128, h2);
    spmm_kernel<<<SPMM_BLOCKS, 256>>>(h2, m);
    gemm_relu_kernel<<<GEMM_BLOCKS, 512, GEMM_SMEM_BYTES>>>(m, Ws + 1 * 128 * 128, bs + 1 * 128, h1);
    spmm_kernel<<<SPMM_BLOCKS, 256>>>(h1, m);
    gemm_relu_kernel<<<GEMM_BLOCKS, 512, GEMM_SMEM_BYTES>>>(m, Ws + 2 * 128 * 128, bs + 2 * 128, h2);

    readout_kernel<<<GG, HH>>>(h2, gid);
    final_kernel<<<(GG * CC + 127) / 128, 128>>>(Wc, bc, out);
}

// round 4
// speedup vs baseline: 3.1471x; 1.1380x over previous
#include <cuda_runtime.h>
#include <math.h>

#define NN 50000
#define EE 800000
#define HH 128
#define CC 10
#define GG 128
#define NBLK 196   // ceil(NN/256)

// ---------------- device scratch (static, no allocation) ----------------
__device__ int   g_outdeg[NN];
__device__ int   g_indeg[NN];
__device__ float g_csrc[NN];
__device__ float g_cdst[NN];
__device__ int   g_rowptr[NN + 1];
__device__ int   g_fill[NN];
__device__ int   g_col[EE];
__device__ float g_m[NN * HH];
__device__ float g_h1[NN * HH];
__device__ float g_h2[NN * HH];
__device__ float g_hg[GG * HH];
__device__ int   g_part[NBLK];

// ---------------- f32x2 helpers ----------------
__device__ __forceinline__ unsigned long long dup2(float a) {
    unsigned long long r;
    asm("mov.b64 %0, {%1, %1};" : "=l"(r) : "f"(a));
    return r;
}
__device__ __forceinline__ void fma2(unsigned long long& acc,
                                     unsigned long long a,
                                     unsigned long long b) {
    asm("fma.rn.f32x2 %0, %1, %2, %0;" : "+l"(acc) : "l"(a), "l"(b));
}
union U2 { unsigned long long u; float2 f; };

// ---------------- preprocessing ----------------

__global__ void zero_kernel() {
    int i = blockIdx.x * blockDim.x + threadIdx.x;
    if (i < NN) { g_outdeg[i] = 0; g_indeg[i] = 0; }
    if (i == 0) g_rowptr[NN] = EE;
}

__global__ void degree_kernel(const int* __restrict__ ei) {
    int e = blockIdx.x * blockDim.x + threadIdx.x;
    if (e >= EE) return;
    atomicAdd(&g_outdeg[ei[e]], 1);
    atomicAdd(&g_indeg[ei[EE + e]], 1);
}

// pass 1: per-block sums of indeg + norm coefficients
__global__ void scan_p1() {
    int t = threadIdx.x;
    int i = blockIdx.x * 256 + t;
    int v = 0;
    if (i < NN) {
        v = g_indeg[i];
        g_csrc[i] = rsqrtf(fmaxf((float)g_outdeg[i], 1.0f));
        g_cdst[i] = rsqrtf(fmaxf((float)v, 1.0f));
    }
    int lane = t & 31, w = t >> 5;
    int x = v;
    #pragma unroll
    for (int o = 16; o > 0; o >>= 1) x += __shfl_down_sync(~0u, x, o);
    __shared__ int ws[8];
    if (lane == 0) ws[w] = x;
    __syncthreads();
    if (t == 0) {
        int s = 0;
        #pragma unroll
        for (int j = 0; j < 8; j++) s += ws[j];
        g_part[blockIdx.x] = s;
    }
}

// pass 2 (merged): each block computes its own offset from g_part, then rescans
__global__ void scan_p3() {
    __shared__ int rs[8];
    __shared__ int ss[8];
    __shared__ int s_off;
    const int t = threadIdx.x, bid = blockIdx.x;
    const int lane = t & 31, w = t >> 5;

    int p = 0;
    for (int j = t; j < bid; j += 256) p += g_part[j];
    int pr = p;
    #pragma unroll
    for (int o = 16; o > 0; o >>= 1) pr += __shfl_down_sync(~0u, pr, o);
    if (lane == 0) rs[w] = pr;
    __syncthreads();
    if (t == 0) {
        int s = 0;
        #pragma unroll
        for (int j = 0; j < 8; j++) s += rs[j];
        s_off = s;
    }
    __syncthreads();
    const int off = s_off;

    int i = bid * 256 + t;
    int v = (i < NN) ? g_indeg[i] : 0;
    int x = v;
    #pragma unroll
    for (int o = 1; o < 32; o <<= 1) {
        int y = __shfl_up_sync(~0u, x, o);
        if (lane >= o) x += y;
    }
    if (lane == 31) ss[w] = x;
    __syncthreads();
    if (t < 8) {
        int s = ss[t];
        #pragma unroll
        for (int o = 1; o < 8; o <<= 1) {
            int y = __shfl_up_sync(0xff, s, o);
            if (t >= o) s += y;
        }
        ss[t] = s;
    }
    __syncthreads();
    int excl = x - v + (w > 0 ? ss[w - 1] : 0) + off;
    if (i < NN) { g_rowptr[i] = excl; g_fill[i] = excl; }
}

__global__ void csr_fill_kernel(const int* __restrict__ ei) {
    int e = blockIdx.x * blockDim.x + threadIdx.x;
    if (e >= EE) return;
    int d = ei[EE + e];
    int pos = atomicAdd(&g_fill[d], 1);
    g_col[pos] = ei[e];
}

// ---------------- GEMM: y = (c_src ⊙ A) @ W  (no bias, no relu) -------------
// 64 rows x 128 cols per block, 256 threads, 96KB smem -> 2 blocks/SM.
// thread: 8 rows x 4 cols -> 16 u64 f32x2 accumulators.
#define GEMM_SMEM ((128 * 128 + 64 * 128) * 4)  // 96KB
__global__ __launch_bounds__(256) void gemm_scale_kernel(
    const float* __restrict__ A, const float* __restrict__ W,
    float* __restrict__ out) {
    extern __shared__ float sm[];
    float* sW = sm;              // [128][128]
    float* sA = sm + 128 * 128;  // [64][128]
    const int t = threadIdx.x;
    const int row0 = blockIdx.x * 64;

    const float4* W4 = (const float4*)W;
    #pragma unroll
    for (int i = t; i < 128 * 32; i += 256) ((float4*)sW)[i] = W4[i];

    const float4* A4 = (const float4*)A;
    #pragma unroll
    for (int i = t; i < 64 * 32; i += 256) {
        int r = i >> 5, kq = i & 31;
        float4 v = make_float4(0.f, 0.f, 0.f, 0.f);
        float cs = 0.f;
        if (row0 + r < NN) { v = A4[(row0 + r) * 32 + kq]; cs = g_csrc[row0 + r]; }
        v.x *= cs; v.y *= cs; v.z *= cs; v.w *= cs;
        ((float4*)sA)[i] = v;
    }
    __syncthreads();

    const int tx = t & 31;   // 4 cols: tx*4
    const int ty = t >> 5;   // 8 rows: ty*8
    const int r0 = ty * 8;

    unsigned long long acc[16];
    #pragma unroll
    for (int p = 0; p < 16; p++) acc[p] = 0ull;

    const ulonglong2* sWu = (const ulonglong2*)sW;
    const float* ap = sA + r0 * 128;

    #pragma unroll 2
    for (int k = 0; k < 128; k++) {
        ulonglong2 wv = sWu[k * 32 + tx];       // LDS.128 conflict-free
        #pragma unroll
        for (int j = 0; j < 8; j++) {
            unsigned long long a = dup2(ap[j * 128 + k]);  // LDS.32 broadcast + movs (alu pipe)
            fma2(acc[2 * j],     a, wv.x);
            fma2(acc[2 * j + 1], a, wv.y);
        }
    }

    float4* out4 = (float4*)out;
    #pragma unroll
    for (int j = 0; j < 8; j++) {
        int r = row0 + r0 + j;
        if (r < NN) {
            U2 ua, ub;
            ua.u = acc[2 * j]; ub.u = acc[2 * j + 1];
            out4[r * 32 + tx] = make_float4(ua.f.x, ua.f.y, ub.f.x, ub.f.y);
        }
    }
}

// ---------------- SpMM: h = relu(c_dst ⊙ (A y) + b), 4-way unroll ----------
__global__ void spmm_bias_relu_kernel(const float* __restrict__ y,
                                      const float* __restrict__ bias,
                                      float* __restrict__ h) {
    int gw = (blockIdx.x * blockDim.x + threadIdx.x) >> 5;
    int lane = threadIdx.x & 31;
    if (gw >= NN) return;
    int e0 = g_rowptr[gw];
    int e1 = g_rowptr[gw + 1];
    const float4* y4 = (const float4*)y;
    float4 a0 = make_float4(0.f, 0.f, 0.f, 0.f);
    float4 a1 = a0, a2 = a0, a3 = a0;
    int e = e0;
    for (; e + 4 <= e1; e += 4) {
        int s0 = g_col[e], s1 = g_col[e + 1], s2 = g_col[e + 2], s3 = g_col[e + 3];
        float4 v0 = y4[s0 * 32 + lane];
        float4 v1 = y4[s1 * 32 + lane];
        float4 v2 = y4[s2 * 32 + lane];
        float4 v3 = y4[s3 * 32 + lane];
        a0.x += v0.x; a0.y += v0.y; a0.z += v0.z; a0.w += v0.w;
        a1.x += v1.x; a1.y += v1.y; a1.z += v1.z; a1.w += v1.w;
        a2.x += v2.x; a2.y += v2.y; a2.z += v2.z; a2.w += v2.w;
        a3.x += v3.x; a3.y += v3.y; a3.z += v3.z; a3.w += v3.w;
    }
    for (; e < e1; e++) {
        int s = g_col[e];
        float4 v = y4[s * 32 + lane];
        a0.x += v.x; a0.y += v.y; a0.z += v.z; a0.w += v.w;
    }
    float cd = g_cdst[gw];
    float4 bv = ((const float4*)bias)[lane];
    float4 o;
    o.x = fmaxf((a0.x + a1.x + a2.x + a3.x) * cd + bv.x, 0.f);
    o.y = fmaxf((a0.y + a1.y + a2.y + a3.y) * cd + bv.y, 0.f);
    o.z = fmaxf((a0.z + a1.z + a2.z + a3.z) * cd + bv.z, 0.f);
    o.w = fmaxf((a0.w + a1.w + a2.w + a3.w) * cd + bv.w, 0.f);
    ((float4*)h)[gw * 32 + lane] = o;
}

// ---------------- readout: one block per graph, binary search, no atomics ----
__global__ void readout_kernel(const float* __restrict__ h, const int* __restrict__ gid) {
    int g = blockIdx.x;
    int f = threadIdx.x;
    int lo = 0, hi = NN;
    while (lo < hi) { int mid = (lo + hi) >> 1; if (gid[mid] < g) lo = mid + 1; else hi = mid; }
    int start = lo;
    lo = start; hi = NN;
    while (lo < hi) { int mid = (lo + hi) >> 1; if (gid[mid] < g + 1) lo = mid + 1; else hi = mid; }
    int end = lo;

    float s = 0.f;
    for (int n = start; n < end; n++) s += h[n * HH + f];
    float cnt = (float)(end - start);
    g_hg[g * HH + f] = s / fmaxf(cnt, 1.0f);
}

__global__ void final_kernel(const float* __restrict__ Wc, const float* __restrict__ bc,
                             float* __restrict__ out) {
    int idx = blockIdx.x * blockDim.x + threadIdx.x;
    if (idx >= GG * CC) return;
    int g = idx / CC, c = idx % CC;
    float sum = 0.f;
    #pragma unroll 8
    for (int k = 0; k < HH; k++) sum = fmaf(g_hg[g * HH + k], Wc[k * CC + c], sum);
    out[idx] = sum + bc[c];
}

// ---------------- host launcher ----------------
extern "C" void kernel_launch(void* const* d_in, const int* in_sizes, int n_in,
                              void* d_out, int out_size) {
    const float* x   = (const float*)d_in[0];
    const float* W0  = (const float*)d_in[1];
    const float* b0  = (const float*)d_in[2];
    const float* Ws  = (const float*)d_in[3];
    const float* bs  = (const float*)d_in[4];
    const float* Wc  = (const float*)d_in[5];
    const float* bc  = (const float*)d_in[6];
    const int*   ei  = (const int*)d_in[7];
    const int*   gid = (const int*)d_in[8];
    float* out = (float*)d_out;

    float *h1, *h2, *m;
    cudaGetSymbolAddress((void**)&h1, g_h1);
    cudaGetSymbolAddress((void**)&h2, g_h2);
    cudaGetSymbolAddress((void**)&m,  g_m);

    cudaFuncSetAttribute(gemm_scale_kernel,
                         cudaFuncAttributeMaxDynamicSharedMemorySize, GEMM_SMEM);

    const int SPMM_BLOCKS = (NN + 7) / 8;
    const int GEMM_BLOCKS = (NN + 63) / 64;

    // preprocessing; layer-0 GEMM hoisted before CSR build (only needs c_src)
    zero_kernel<<<(NN + 255) / 256, 256>>>();
    degree_kernel<<<(EE + 255) / 256, 256>>>(ei);
    scan_p1<<<NBLK, 256>>>();
    gemm_scale_kernel<<<GEMM_BLOCKS, 256, GEMM_SMEM>>>(x, W0, m);   // <- profiled (idx 3)
    scan_p3<<<NBLK, 256>>>();
    csr_fill_kernel<<<(EE + 255) / 256, 256>>>(ei);

    // layer 0 aggregation
    spmm_bias_relu_kernel<<<SPMM_BLOCKS, 256>>>(m, b0, h1);
    // layers 1..3
    gemm_scale_kernel<<<GEMM_BLOCKS, 256, GEMM_SMEM>>>(h1, Ws + 0 * 128 * 128, m);
    spmm_bias_relu_kernel<<<SPMM_BLOCKS, 256>>>(m, bs + 0 * 128, h2);
    gemm_scale_kernel<<<GEMM_BLOCKS, 256, GEMM_SMEM>>>(h2, Ws + 1 * 128 * 128, m);
    spmm_bias_relu_kernel<<<SPMM_BLOCKS, 256>>>(m, bs + 1 * 128, h1);
    gemm_scale_kernel<<<GEMM_BLOCKS, 256, GEMM_SMEM>>>(h1, Ws + 2 * 128 * 128, m);
    spmm_bias_relu_kernel<<<SPMM_BLOCKS, 256>>>(m, bs + 2 * 128, h2);

    readout_kernel<<<GG, HH>>>(h2, gid);
    final_kernel<<<(GG * CC + 127) / 128, 128>>>(Wc, bc, out);
}